// round 2
// baseline (speedup 1.0000x reference)
#include <cuda_runtime.h>

#define N_SAMPLES   8192
#define N_CHANNELS  1024
#define N_COMP      4
#define THREADS     256
#define CH          8            // channels per thread
#define SPB         8            // samples per block
#define PAD         8
#define ROW_LEN     1040         // padded words per component row (mult of 8)
#define SMEM_WORDS  4352         // 4*1040=4160 rounded up to 1024B multiple (swizzle safety)

// word-level SW128 swizzle: byte b ^ ((b>>3)&0x70)  ==  word w ^ ((w>>3)&0x1C)
__device__ __forceinline__ int swzw(int w) { return w ^ ((w >> 3) & 0x1C); }

#define TAPS(t0,t1,t2,t3,t4,t5,t6,t7,t8)                     \
    acc0 += a*(t0) + b*(t1);  acc1 += a*(t1) + b*(t2);       \
    acc2 += a*(t2) + b*(t3);  acc3 += a*(t3) + b*(t4);       \
    acc4 += a*(t4) + b*(t5);  acc5 += a*(t5) + b*(t6);       \
    acc6 += a*(t6) + b*(t7);  acc7 += a*(t7) + b*(t8);

__global__ void __launch_bounds__(THREADS)
smf_kernel(const float* __restrict__ comp,      // [4, 1024]
           const float* __restrict__ contrib,   // [8192, 4]
           const float* __restrict__ shift,     // [8192, 4]
           float* __restrict__ out)             // [8192, 1024]
{
    __shared__ __align__(128) float scomp[SMEM_WORDS];
    __shared__ float s_shift[SPB * N_COMP];
    __shared__ float s_contrib[SPB * N_COMP];

    const int tid   = threadIdx.x;
    const int sbase = blockIdx.x * SPB;

    // Fill swizzled, zero-padded component rows (float4 granularity).
    {
        const float4* c4 = (const float4*)comp;
        float4* s4w = (float4*)scomp;
        #pragma unroll
        for (int q = tid; q < N_COMP * (ROW_LEN / 4); q += THREADS) {
            int k  = q / (ROW_LEN / 4);
            int pq = q - k * (ROW_LEN / 4);      // float4 index within padded row
            int jq = pq - PAD / 4;               // source float4 index
            float4 v = make_float4(0.f, 0.f, 0.f, 0.f);
            if (jq >= 0 && jq < N_CHANNELS / 4) v = c4[k * (N_CHANNELS / 4) + jq];
            s4w[swzw(q * 4) >> 2] = v;
        }
    }
    if (tid < SPB * N_COMP) {
        s_shift[tid]   = shift[sbase * N_COMP + tid];
        s_contrib[tid] = contrib[sbase * N_COMP + tid];
    }
    __syncthreads();

    const float4* s4 = (const float4*)scomp;

    // 256 threads = 2 concurrent samples x 128 threads x 8 channels
    const int half = tid >> 7;                 // which sample of the pair
    const int i0   = (tid & 127) * CH;         // first channel of this thread

    #pragma unroll
    for (int sp = 0; sp < SPB; sp += 2) {
        const int s = sp + half;
        float acc0 = 0.f, acc1 = 0.f, acc2 = 0.f, acc3 = 0.f;
        float acc4 = 0.f, acc5 = 0.f, acc6 = 0.f, acc7 = 0.f;

        #pragma unroll
        for (int k = 0; k < N_COMP; k++) {
            // warp-uniform per-(sample,k) parameters
            const float sh = s_shift[s * N_COMP + k];
            const float cn = s_contrib[s * N_COMP + k];
            const float ff = floorf(sh);
            const int   fi = (int)ff;
            const float fr = sh - ff;
            const float b  = cn * fr;          // weight of tap j+1
            const float a  = cn - b;           // cn*(1-fr)

            const int p  = i0 + fi + PAD;      // first tap (padded index)
            const int w0 = k * ROW_LEN + (p & ~3);
            const int r  = p & 3;              // uniform across the block

            const float4 v0 = s4[swzw(w0)     >> 2];
            const float4 v1 = s4[swzw(w0 + 4) >> 2];
            const float4 v2 = s4[swzw(w0 + 8) >> 2];

            switch (r) {
                case 0:  TAPS(v0.x, v0.y, v0.z, v0.w, v1.x, v1.y, v1.z, v1.w, v2.x) break;
                case 1:  TAPS(v0.y, v0.z, v0.w, v1.x, v1.y, v1.z, v1.w, v2.x, v2.y) break;
                case 2:  TAPS(v0.z, v0.w, v1.x, v1.y, v1.z, v1.w, v2.x, v2.y, v2.z) break;
                default: TAPS(v0.w, v1.x, v1.y, v1.z, v1.w, v2.x, v2.y, v2.z, v2.w) break;
            }
        }

        float4* o4 = (float4*)out + (size_t)(sbase + s) * (N_CHANNELS / 4) + (i0 >> 2);
        o4[0] = make_float4(acc0, acc1, acc2, acc3);
        o4[1] = make_float4(acc4, acc5, acc6, acc7);
    }
}

extern "C" void kernel_launch(void* const* d_in, const int* in_sizes, int n_in,
                              void* d_out, int out_size)
{
    // inputs [8192,1024] (ignored), components [4,1024],
    // contributions [8192,4], shift [8192,4]
    const float* comp    = (const float*)d_in[1];
    const float* contrib = (const float*)d_in[2];
    const float* shift   = (const float*)d_in[3];
    float* out           = (float*)d_out;

    smf_kernel<<<N_SAMPLES / SPB, THREADS>>>(comp, contrib, shift, out);
}

// round 3
// speedup vs baseline: 1.0467x; 1.0467x over previous
#include <cuda_runtime.h>

#define N_SAMPLES   8192
#define N_CHANNELS  1024
#define N_COMP      4
#define THREADS     128          // 1 sample slice per thread: 8 channels each
#define SPB         8            // samples per block
#define CH          8

#define TAPS(t0,t1,t2,t3,t4,t5,t6,t7,t8)                     \
    acc0 += a*(t0) + b*(t1);  acc1 += a*(t1) + b*(t2);       \
    acc2 += a*(t2) + b*(t3);  acc3 += a*(t3) + b*(t4);       \
    acc4 += a*(t4) + b*(t5);  acc5 += a*(t5) + b*(t6);       \
    acc6 += a*(t6) + b*(t7);  acc7 += a*(t7) + b*(t8);

__global__ void __launch_bounds__(THREADS)
smf_kernel(const float* __restrict__ comp,      // [4, 1024]
           const float* __restrict__ contrib,   // [8192, 4]
           const float* __restrict__ shift,     // [8192, 4]
           float* __restrict__ out)             // [8192, 1024]
{
    const int tid   = threadIdx.x;
    const int i0    = tid * CH;                 // this thread's first channel
    const int sbase = blockIdx.x * SPB;

    // Register-resident component window: c[k][q] = comp[k, i0-4+4q .. +3]
    // Covers every tap reachable for fi in [-4,3]. Out-of-range -> 0.
    float4 c[N_COMP][4];
    #pragma unroll
    for (int k = 0; k < N_COMP; k++) {
        #pragma unroll
        for (int q = 0; q < 4; q++) {
            const int j = i0 - 4 + 4 * q;       // float4-aligned
            if (j >= 0 && j < N_CHANNELS)
                c[k][q] = __ldg((const float4*)(comp + k * N_CHANNELS + j));
            else
                c[k][q] = make_float4(0.f, 0.f, 0.f, 0.f);
        }
    }

    for (int sp = 0; sp < SPB; sp++) {
        const int s = sbase + sp;
        // per-sample params: one float4 row each, uniform across block (L1 broadcast)
        const float4 sh4 = __ldg((const float4*)(shift   + s * N_COMP));
        const float4 cn4 = __ldg((const float4*)(contrib + s * N_COMP));
        const float shv[N_COMP] = { sh4.x, sh4.y, sh4.z, sh4.w };
        const float cnv[N_COMP] = { cn4.x, cn4.y, cn4.z, cn4.w };

        float acc0 = 0.f, acc1 = 0.f, acc2 = 0.f, acc3 = 0.f;
        float acc4 = 0.f, acc5 = 0.f, acc6 = 0.f, acc7 = 0.f;

        #pragma unroll
        for (int k = 0; k < N_COMP; k++) {
            const float sh = shv[k];
            const float cn = cnv[k];
            const float ff = floorf(sh);
            int   fi = (int)ff;
            float fr = sh - ff;
            if (fi > 3)  { fr += (float)(fi - 3); fi = 3; }   // handles shift == 4.0
            if (fi < -4) { fi = -4; }                          // OOB safety only

            const float b = cn * fr;            // weight of tap j+1
            const float a = cn - b;             // cn*(1-fr)

            const int w = fi + 4;               // window start word in [0,7]
            const int u = w >> 2;               // which quad pair {0,1} (uniform)
            const int r = w & 3;                // intra-quad offset (uniform)

            const float4 v0 = u ? c[k][1] : c[k][0];
            const float4 v1 = u ? c[k][2] : c[k][1];
            const float4 v2 = u ? c[k][3] : c[k][2];

            switch (r) {                        // uniform across block
                case 0:  TAPS(v0.x, v0.y, v0.z, v0.w, v1.x, v1.y, v1.z, v1.w, v2.x) break;
                case 1:  TAPS(v0.y, v0.z, v0.w, v1.x, v1.y, v1.z, v1.w, v2.x, v2.y) break;
                case 2:  TAPS(v0.z, v0.w, v1.x, v1.y, v1.z, v1.w, v2.x, v2.y, v2.z) break;
                default: TAPS(v0.w, v1.x, v1.y, v1.z, v1.w, v2.x, v2.y, v2.z, v2.w) break;
            }
        }

        float4* o4 = (float4*)out + (size_t)s * (N_CHANNELS / 4) + (i0 >> 2);
        o4[0] = make_float4(acc0, acc1, acc2, acc3);
        o4[1] = make_float4(acc4, acc5, acc6, acc7);
    }
}

extern "C" void kernel_launch(void* const* d_in, const int* in_sizes, int n_in,
                              void* d_out, int out_size)
{
    // inputs [8192,1024] (ignored), components [4,1024],
    // contributions [8192,4], shift [8192,4]
    const float* comp    = (const float*)d_in[1];
    const float* contrib = (const float*)d_in[2];
    const float* shift   = (const float*)d_in[3];
    float* out           = (float*)d_out;

    smf_kernel<<<N_SAMPLES / SPB, THREADS>>>(comp, contrib, shift, out);
}

// round 4
// speedup vs baseline: 1.1568x; 1.1052x over previous
#include <cuda_runtime.h>

#define N_SAMPLES   8192
#define N_CHANNELS  1024
#define N_COMP      4
#define THREADS     128          // 8 channels per thread
#define SPB         8            // samples per block
#define CH          8

__global__ void __launch_bounds__(THREADS)
smf_kernel(const float* __restrict__ comp,      // [4, 1024]
           const float* __restrict__ contrib,   // [8192, 4]
           const float* __restrict__ shift,     // [8192, 4]
           float* __restrict__ out)             // [8192, 1024]
{
    // per-(sample,comp) params: {w0, w1, w2, bitcast(u2)}
    __shared__ __align__(16) float4 sP[SPB][N_COMP];

    const int tid   = threadIdx.x;
    const int i0    = tid * CH;
    const int sbase = blockIdx.x * SPB;

    // ---- precompute (32 threads, one per (s,k)) ----
    if (tid < SPB * N_COMP) {
        const int s = tid >> 2, k = tid & 3;
        const float sh = shift[(sbase + s) * N_COMP + k];
        const float cn = contrib[(sbase + s) * N_COMP + k];
        const int   fi = (int)floorf(sh);          // in [-4, 3]
        const int   g  = fi & ~1;                  // even window base in {-4,-2,0,2}
        const int   u2 = (g + 4) >> 1;             // in [0,3]
        const float x  = sh - (float)g;            // in [0, 2)
        // 3-tap weights: w_j = cn * max(0, 1 - |j - x|); exactly 2 are nonzero
        const float w0 = cn * fmaxf(0.0f, 1.0f - fabsf(0.0f - x));
        const float w1 = cn * fmaxf(0.0f, 1.0f - fabsf(1.0f - x));
        const float w2 = cn * fmaxf(0.0f, 1.0f - fabsf(2.0f - x));
        sP[s][k] = make_float4(w0, w1, w2, __int_as_float(u2));
    }

    // ---- register-resident window: cf[k][t] = comp[k, i0-4+t], t in [0,16) ----
    float cf[N_COMP][16];
    #pragma unroll
    for (int k = 0; k < N_COMP; k++) {
        #pragma unroll
        for (int q = 0; q < 4; q++) {
            const int j = i0 - 4 + 4 * q;          // float4-aligned
            float4 v = make_float4(0.f, 0.f, 0.f, 0.f);
            if (j >= 0 && j < N_CHANNELS)
                v = __ldg((const float4*)(comp + k * N_CHANNELS + j));
            cf[k][4*q+0] = v.x; cf[k][4*q+1] = v.y;
            cf[k][4*q+2] = v.z; cf[k][4*q+3] = v.w;
        }
    }
    __syncthreads();

    #pragma unroll 2
    for (int s = 0; s < SPB; s++) {
        float acc[CH];
        #pragma unroll
        for (int i = 0; i < CH; i++) acc[i] = 0.f;

        #pragma unroll
        for (int k = 0; k < N_COMP; k++) {
            const float4 p = sP[s][k];             // LDS.128 broadcast
            const float w0 = p.x, w1 = p.y, w2 = p.z;
            const int   u2 = __float_as_int(p.w);
            const bool  b1 = (u2 & 2) != 0;        // shift window by 4 floats
            const bool  b0 = (u2 & 1) != 0;        // shift window by 2 floats

            float m[12];
            #pragma unroll
            for (int t = 0; t < 12; t++) m[t] = b1 ? cf[k][t + 4] : cf[k][t];
            float v[10];
            #pragma unroll
            for (int t = 0; t < 10; t++) v[t] = b0 ? m[t + 2] : m[t];

            #pragma unroll
            for (int i = 0; i < CH; i++)
                acc[i] += w0 * v[i] + w1 * v[i + 1] + w2 * v[i + 2];
        }

        float4* o4 = (float4*)out + (size_t)(sbase + s) * (N_CHANNELS / 4) + (i0 >> 2);
        o4[0] = make_float4(acc[0], acc[1], acc[2], acc[3]);
        o4[1] = make_float4(acc[4], acc[5], acc[6], acc[7]);
    }
}

extern "C" void kernel_launch(void* const* d_in, const int* in_sizes, int n_in,
                              void* d_out, int out_size)
{
    // inputs [8192,1024] (ignored), components [4,1024],
    // contributions [8192,4], shift [8192,4]
    const float* comp    = (const float*)d_in[1];
    const float* contrib = (const float*)d_in[2];
    const float* shift   = (const float*)d_in[3];
    float* out           = (float*)d_out;

    smf_kernel<<<N_SAMPLES / SPB, THREADS>>>(comp, contrib, shift, out);
}